// round 1
// baseline (speedup 1.0000x reference)
#include <cuda_runtime.h>
#include <cstdint>

#define H      128
#define BM     128
#define LDA    132        // padded SMEM row (floats) for the activation tile
#define TPB    256
#define LN_EPS 1e-5f

typedef unsigned long long u64;

// ---- packed f32x2 helpers (sm_103a FFMA2: full-rate vs half-rate FFMA-3reg) ----
__device__ __forceinline__ u64 pack2(float v) {
    u64 d; asm("mov.b64 %0, {%1, %1};" : "=l"(d) : "f"(v)); return d;
}
__device__ __forceinline__ u64 pack2f(float lo, float hi) {
    u64 d; asm("mov.b64 %0, {%1, %2};" : "=l"(d) : "f"(lo), "f"(hi)); return d;
}
__device__ __forceinline__ void unpack2(u64 v, float& lo, float& hi) {
    asm("mov.b64 {%0, %1}, %2;" : "=f"(lo), "=f"(hi) : "l"(v));
}
__device__ __forceinline__ u64 ffma2(u64 a, u64 b, u64 c) {
    u64 d; asm("fma.rn.f32x2 %0, %1, %2, %3;" : "=l"(d) : "l"(a), "l"(b), "l"(c)); return d;
}

// Thread (ty, tx) in a 16x16 grid owns rows m = ty*8..ty*8+7 and
// columns n = {tx*4+0..3, 64+tx*4+0..3}  (two contiguous float4 groups so
// Ws reads are conflict-free LDS.128 with half-warp dedup).
__device__ __forceinline__ int n_of(int tx, int j) {
    return (j < 4) ? (tx * 4 + j) : (64 + tx * 4 + (j - 4));
}

// One 128x128x128 GEMM chunk: C[m][n] += A[m][k] * W[k][n]
__device__ __forceinline__ void gemm_accum(const float* __restrict__ As,
                                           const float* __restrict__ Ws,
                                           int ty, int tx, u64 acc[8][4]) {
    const float* arow = As + ty * 8 * LDA;
#pragma unroll 4
    for (int kk = 0; kk < 128; kk++) {
        u64 a2[8];
#pragma unroll
        for (int i = 0; i < 8; i++) a2[i] = pack2(arow[i * LDA + kk]);
        float4 blo = *(const float4*)(Ws + kk * 128 + tx * 4);
        float4 bhi = *(const float4*)(Ws + kk * 128 + tx * 4 + 64);
        u64 b2[4];
        b2[0] = pack2f(blo.x, blo.y);
        b2[1] = pack2f(blo.z, blo.w);
        b2[2] = pack2f(bhi.x, bhi.y);
        b2[3] = pack2f(bhi.z, bhi.w);
#pragma unroll
        for (int i = 0; i < 8; i++) {
#pragma unroll
            for (int j = 0; j < 4; j++) acc[i][j] = ffma2(a2[i], b2[j], acc[i][j]);
        }
    }
}

// bias add + LayerNorm (row reduction over 128 cols via 16-lane shfl) + ReLU
__device__ __forceinline__ void ln_relu(const u64 acc[8][4], float c[8][8],
                                        const float* __restrict__ bias,
                                        const float* __restrict__ gamma,
                                        const float* __restrict__ beta, int tx) {
    float bb[8], gg[8], be[8];
#pragma unroll
    for (int j = 0; j < 8; j++) {
        int n = n_of(tx, j);
        bb[j] = bias[n]; gg[j] = gamma[n]; be[j] = beta[n];
    }
#pragma unroll
    for (int i = 0; i < 8; i++) {
#pragma unroll
        for (int j2 = 0; j2 < 4; j2++) {
            float lo, hi; unpack2(acc[i][j2], lo, hi);
            c[i][2 * j2]     = lo + bb[2 * j2];
            c[i][2 * j2 + 1] = hi + bb[2 * j2 + 1];
        }
    }
#pragma unroll
    for (int i = 0; i < 8; i++) {
        float s1 = 0.f, s2 = 0.f;
#pragma unroll
        for (int j = 0; j < 8; j++) { s1 += c[i][j]; s2 += c[i][j] * c[i][j]; }
#pragma unroll
        for (int o = 8; o >= 1; o >>= 1) {
            s1 += __shfl_xor_sync(0xffffffffu, s1, o);
            s2 += __shfl_xor_sync(0xffffffffu, s2, o);
        }
        float mu  = s1 * (1.0f / 128.0f);
        float var = s2 * (1.0f / 128.0f) - mu * mu;
        float rs  = rsqrtf(var + LN_EPS);
#pragma unroll
        for (int j = 0; j < 8; j++) {
            float v = (c[i][j] - mu) * rs * gg[j] + be[j];
            c[i][j] = fmaxf(v, 0.0f);
        }
    }
}

__device__ __forceinline__ void store_h(float* __restrict__ As, const float c[8][8],
                                        int ty, int tx) {
#pragma unroll
    for (int i = 0; i < 8; i++) {
        float* row = As + (ty * 8 + i) * LDA;
        *(float2*)(row + tx * 4)          = make_float2(c[i][0], c[i][1]);
        *(float2*)(row + tx * 4 + 2)      = make_float2(c[i][2], c[i][3]);
        *(float2*)(row + 64 + tx * 4)     = make_float2(c[i][4], c[i][5]);
        *(float2*)(row + 64 + tx * 4 + 2) = make_float2(c[i][6], c[i][7]);
    }
}

__device__ __forceinline__ void zero_acc(u64 acc[8][4]) {
#pragma unroll
    for (int i = 0; i < 8; i++)
#pragma unroll
        for (int j = 0; j < 4; j++) acc[i][j] = 0ull;
}

extern "C" __global__ void __launch_bounds__(TPB, 1)
edge_mlp_kernel(float* __restrict__ out,
                const float* __restrict__ x,
                const int* __restrict__ ei,      // [2, E] (src row, then dst row)
                const float* __restrict__ edge,
                const float* __restrict__ W0, const float* __restrict__ b0,
                const float* __restrict__ g0, const float* __restrict__ be0,
                const float* __restrict__ W1, const float* __restrict__ b1,
                const float* __restrict__ g1, const float* __restrict__ be1,
                const float* __restrict__ W2, const float* __restrict__ b2,
                const float* __restrict__ g2, const float* __restrict__ be2,
                const float* __restrict__ W3, const float* __restrict__ b3,
                int E) {
    extern __shared__ float sm[];
    float* As = sm;                // [128][LDA]
    float* Ws = sm + BM * LDA;     // [128][128]

    const int tid = threadIdx.x;
    const int ty = tid >> 4;
    const int tx = tid & 15;
    const long base = (long)blockIdx.x * BM;

    u64 acc[8][4];
    zero_acc(acc);

    // ---------------- GEMM0: [128,384] @ W0[384,128], 3 K-chunks ----------------
    for (int chunk = 0; chunk < 3; chunk++) {
        // weights chunk (contiguous 64KB copy; warp = one 512B row)
        const float4* wsrc = (const float4*)(W0 + (size_t)chunk * 128 * 128);
        float4* wdst = (float4*)Ws;
#pragma unroll
        for (int it = 0; it < 16; it++) {
            int idx = tid + it * TPB;
            wdst[idx] = wsrc[idx];
        }
        // gathered activation chunk: chunk0 = x[src], chunk1 = x[dst], chunk2 = edge
#pragma unroll
        for (int it = 0; it < 16; it++) {
            int idx = tid + it * TPB;
            int m = idx >> 5, cc = idx & 31;      // warp covers one full 512B row
            long e = base + m; if (e >= E) e = E - 1;
            const float* srcp;
            if (chunk == 0)      srcp = x + (size_t)ei[e] * H;
            else if (chunk == 1) srcp = x + (size_t)ei[(size_t)E + e] * H;
            else                 srcp = edge + (size_t)e * H;
            float4 v = ((const float4*)srcp)[cc];
            *(float4*)(As + m * LDA + cc * 4) = v;
        }
        __syncthreads();
        gemm_accum(As, Ws, ty, tx, acc);
        __syncthreads();
    }

    float c[8][8];
    ln_relu(acc, c, b0, g0, be0, tx);

    // ---------------- GEMM1 ----------------
    store_h(As, c, ty, tx);
    {
        const float4* wsrc = (const float4*)W1;
        float4* wdst = (float4*)Ws;
#pragma unroll
        for (int it = 0; it < 16; it++) { int idx = tid + it * TPB; wdst[idx] = wsrc[idx]; }
    }
    __syncthreads();
    zero_acc(acc);
    gemm_accum(As, Ws, ty, tx, acc);
    __syncthreads();
    ln_relu(acc, c, b1, g1, be1, tx);

    // ---------------- GEMM2 ----------------
    store_h(As, c, ty, tx);
    {
        const float4* wsrc = (const float4*)W2;
        float4* wdst = (float4*)Ws;
#pragma unroll
        for (int it = 0; it < 16; it++) { int idx = tid + it * TPB; wdst[idx] = wsrc[idx]; }
    }
    __syncthreads();
    zero_acc(acc);
    gemm_accum(As, Ws, ty, tx, acc);
    ln_relu(acc, c, b2, g2, be2, tx);

    // ---------------- final matvec: out = h @ W3 + b3 ----------------
    float w3v[8];
#pragma unroll
    for (int j = 0; j < 8; j++) w3v[j] = W3[n_of(tx, j)];
    const float bias3 = b3[0];
#pragma unroll
    for (int i = 0; i < 8; i++) {
        float p = 0.f;
#pragma unroll
        for (int j = 0; j < 8; j++) p += c[i][j] * w3v[j];
#pragma unroll
        for (int o = 8; o >= 1; o >>= 1) p += __shfl_xor_sync(0xffffffffu, p, o);
        long e = base + ty * 8 + i;
        if (tx == 0 && e < E) out[e] = p + bias3;
    }
}

#define SMEM_BYTES ((BM * LDA + 128 * 128) * 4)

extern "C" void kernel_launch(void* const* d_in, const int* in_sizes, int n_in,
                              void* d_out, int out_size) {
    const float* x    = (const float*)d_in[0];
    const int*   ei   = (const int*)d_in[1];   // jax canonicalizes int64 -> int32
    const float* edge = (const float*)d_in[2];
    const float* W0   = (const float*)d_in[3];
    const float* b0   = (const float*)d_in[4];
    const float* g0   = (const float*)d_in[5];
    const float* be0  = (const float*)d_in[6];
    const float* W1   = (const float*)d_in[7];
    const float* b1   = (const float*)d_in[8];
    const float* g1   = (const float*)d_in[9];
    const float* be1  = (const float*)d_in[10];
    const float* W2   = (const float*)d_in[11];
    const float* b2   = (const float*)d_in[12];
    const float* g2   = (const float*)d_in[13];
    const float* be2  = (const float*)d_in[14];
    const float* W3   = (const float*)d_in[15];
    const float* b3   = (const float*)d_in[16];

    int E = out_size;  // one output per edge
    cudaFuncSetAttribute(edge_mlp_kernel,
                         cudaFuncAttributeMaxDynamicSharedMemorySize, SMEM_BYTES);
    dim3 grid((E + BM - 1) / BM);
    edge_mlp_kernel<<<grid, TPB, SMEM_BYTES>>>(
        (float*)d_out, x, ei, edge,
        W0, b0, g0, be0, W1, b1, g1, be1, W2, b2, g2, be2, W3, b3, E);
}

// round 3
// speedup vs baseline: 3.3850x; 3.3850x over previous
#include <cuda_runtime.h>
#include <cuda_fp16.h>
#include <cstdint>

#define TPB    256
#define BM     128
#define H      128
#define LDAH   136          // padded A/B row stride in halves (272B: conflict-free ldmatrix)
#define LN_EPS 1e-5f

// SMEM layout (bytes)
#define SM_PAR   0          // 1281 floats of params (5124B)
#define SM_A     5632       // 128 x LDAH halves = 34816B
#define SM_B     40448      // 128 x LDAH halves = 34816B
#define SM_TOTAL 75264

// 5 pre-transposed fp16 weight tiles: [tile][n=128][k=128]
__device__ __align__(16) __half g_wt[5 * 16384];

__device__ __forceinline__ uint32_t smem_u32(const void* p) {
    uint32_t a;
    asm("{ .reg .u64 t; cvta.to.shared.u64 t, %1; cvt.u32.u64 %0, t; }"
        : "=r"(a) : "l"(p));
    return a;
}

#define LDMATRIX_X4(r0, r1, r2, r3, addr)                                      \
    asm volatile("ldmatrix.sync.aligned.m8n8.x4.shared.b16 {%0,%1,%2,%3}, [%4];" \
                 : "=r"(r0), "=r"(r1), "=r"(r2), "=r"(r3) : "r"(addr))

#define MMA16816(d, a0, a1, a2, a3, bb0, bb1)                                  \
    asm volatile("mma.sync.aligned.m16n8k16.row.col.f32.f16.f16.f32 "          \
                 "{%0,%1,%2,%3}, {%4,%5,%6,%7}, {%8,%9}, {%0,%1,%2,%3};"       \
                 : "+f"((d)[0]), "+f"((d)[1]), "+f"((d)[2]), "+f"((d)[3])      \
                 : "r"(a0), "r"(a1), "r"(a2), "r"(a3), "r"(bb0), "r"(bb1))

// ---------------- prep: transpose + fp16-convert weights ----------------
__global__ void prep_kernel(const float* __restrict__ W0,
                            const float* __restrict__ W1,
                            const float* __restrict__ W2) {
    int idx = blockIdx.x * blockDim.x + threadIdx.x;
    if (idx >= 5 * 16384) return;
    int t = idx >> 14, r = idx & 16383, n = r >> 7, k = r & 127;
    float v;
    if (t < 3)       v = W0[(t * 128 + k) * 128 + n];
    else if (t == 3) v = W1[k * 128 + n];
    else             v = W2[k * 128 + n];
    g_wt[idx] = __float2half_rn(v);
}

// ---------------- main fused kernel ----------------
extern "C" __global__ void __launch_bounds__(TPB, 2)
edge_mlp_hmma(float* __restrict__ out,
              const float* __restrict__ x, const int* __restrict__ ei,
              const float* __restrict__ edge,
              const float* __restrict__ b0, const float* __restrict__ g0, const float* __restrict__ be0,
              const float* __restrict__ b1, const float* __restrict__ g1, const float* __restrict__ be1,
              const float* __restrict__ b2, const float* __restrict__ g2, const float* __restrict__ be2,
              const float* __restrict__ W3, const float* __restrict__ b3,
              int E) {
    extern __shared__ char smem[];
    float* smf = (float*)smem;
    const uint32_t sb = smem_u32(smem);
    const int tid = threadIdx.x, wid = tid >> 5, lane = tid & 31;
    const int base = blockIdx.x * BM;

    // stage LN params + W3/b3 (fp32)
    for (int i = tid; i < 128; i += TPB) {
        smf[0 * 384 + i] = b0[i]; smf[0 * 384 + 128 + i] = g0[i]; smf[0 * 384 + 256 + i] = be0[i];
        smf[1 * 384 + i] = b1[i]; smf[1 * 384 + 128 + i] = g1[i]; smf[1 * 384 + 256 + i] = be1[i];
        smf[2 * 384 + i] = b2[i]; smf[2 * 384 + 128 + i] = g2[i]; smf[2 * 384 + 256 + i] = be2[i];
        smf[1152 + i] = W3[i];
    }
    if (tid == 0) smf[1280] = b3[0];

    // ldmatrix lane addressing
    const int arow = (lane & 7) + ((lane >> 3) & 1) * 8;   // A: m within strip
    const int acol = (lane >> 4) * 8;                      // A: k offset
    const uint32_t aaddr = sb + SM_A + (uint32_t)((wid * 16 + arow) * LDAH + acol) * 2;
    const int bn = (lane & 7) + ((lane >> 4) & 1) * 8;     // B: n within 2-tile group
    const int bk = ((lane >> 3) & 1) * 8;                  // B: k offset
    const uint32_t baddr = sb + SM_B + (uint32_t)(bn * LDAH + bk) * 2;

    float acc[16][4];
#pragma unroll
    for (int i = 0; i < 16; i++)
#pragma unroll
        for (int j = 0; j < 4; j++) acc[i][j] = 0.f;

    auto stage_b = [&](int t) {
        const uint4* src = (const uint4*)(g_wt + t * 16384);
#pragma unroll
        for (int i = 0; i < 8; i++) {
            int u = tid + i * 256;
            uint4 v = __ldg(&src[u]);
            *(uint4*)(smem + SM_B + (u >> 4) * 272 + (u & 15) * 16) = v;
        }
    };

    auto mma_chunk = [&]() {
        for (int ks = 0; ks < 8; ks++) {
            uint32_t a0, a1, a2, a3;
            LDMATRIX_X4(a0, a1, a2, a3, aaddr + ks * 32);
#pragma unroll
            for (int g = 0; g < 8; g++) {
                uint32_t c0, c1, c2, c3;
                LDMATRIX_X4(c0, c1, c2, c3, baddr + g * 4352 + ks * 32);
                MMA16816(acc[2 * g],     a0, a1, a2, a3, c0, c1);
                MMA16816(acc[2 * g + 1], a0, a1, a2, a3, c2, c3);
            }
        }
    };

    // ---------------- layer 0: K=384 in 3 gathered chunks ----------------
    for (int g = 0; g < 3; g++) {
        // gather this warp's own 16 rows, convert to fp16
        for (int r = 0; r < 16; r++) {
            int m = wid * 16 + r;
            int e = base + m; if (e >= E) e = E - 1;
            const float* src;
            if (g == 0)      src = x + (size_t)ei[e] * H;
            else if (g == 1) src = x + (size_t)ei[(size_t)E + e] * H;
            else             src = edge + (size_t)e * H;
            float4 v = __ldg((const float4*)src + lane);
            __half2 h0 = __floats2half2_rn(v.x, v.y);
            __half2 h1 = __floats2half2_rn(v.z, v.w);
            uint2 u = make_uint2(*(uint32_t*)&h0, *(uint32_t*)&h1);
            *(uint2*)(smem + SM_A + m * 272 + lane * 8) = u;
        }
        stage_b(g);
        __syncthreads();
        mma_chunk();
        __syncthreads();
    }

    // LN epilogue: warp-local. Row mlo = wid*16 + lane/4 (acc regs 0,1),
    // row mhi = mlo+8 (acc regs 2,3); cols n = nt*8 + 2*(lane&3) + {0,1}.
    const int c2 = 2 * (lane & 3);
    const int mlo = wid * 16 + (lane >> 2);
    const int mhi = mlo + 8;

    auto epilogue = [&](int l, bool last) {
        const float* pb = smf + l * 384;
        const float* pg = pb + 128;
        const float* pe = pb + 256;
        float s1l = 0.f, s2l = 0.f, s1h = 0.f, s2h = 0.f;
#pragma unroll
        for (int nt = 0; nt < 16; nt++) {
            int n0 = nt * 8 + c2;
            float bia0 = pb[n0], bia1 = pb[n0 + 1];
            acc[nt][0] += bia0; acc[nt][1] += bia1;
            acc[nt][2] += bia0; acc[nt][3] += bia1;
            s1l += acc[nt][0] + acc[nt][1];
            s2l += acc[nt][0] * acc[nt][0] + acc[nt][1] * acc[nt][1];
            s1h += acc[nt][2] + acc[nt][3];
            s2h += acc[nt][2] * acc[nt][2] + acc[nt][3] * acc[nt][3];
        }
#pragma unroll
        for (int o = 1; o <= 2; o <<= 1) {
            s1l += __shfl_xor_sync(0xffffffffu, s1l, o);
            s2l += __shfl_xor_sync(0xffffffffu, s2l, o);
            s1h += __shfl_xor_sync(0xffffffffu, s1h, o);
            s2h += __shfl_xor_sync(0xffffffffu, s2h, o);
        }
        float mul = s1l * (1.0f / 128.0f);
        float rsl = rsqrtf(s2l * (1.0f / 128.0f) - mul * mul + LN_EPS);
        float muh = s1h * (1.0f / 128.0f);
        float rsh = rsqrtf(s2h * (1.0f / 128.0f) - muh * muh + LN_EPS);

        if (!last) {
#pragma unroll
            for (int nt = 0; nt < 16; nt++) {
                int n0 = nt * 8 + c2;
                float ga0 = pg[n0], ga1 = pg[n0 + 1], ea0 = pe[n0], ea1 = pe[n0 + 1];
                float v0 = fmaxf((acc[nt][0] - mul) * rsl * ga0 + ea0, 0.f);
                float v1 = fmaxf((acc[nt][1] - mul) * rsl * ga1 + ea1, 0.f);
                __half2 hl = __floats2half2_rn(v0, v1);
                *(uint32_t*)(smem + SM_A + mlo * 272 + n0 * 2) = *(uint32_t*)&hl;
                float w0 = fmaxf((acc[nt][2] - muh) * rsh * ga0 + ea0, 0.f);
                float w1 = fmaxf((acc[nt][3] - muh) * rsh * ga1 + ea1, 0.f);
                __half2 hh = __floats2half2_rn(w0, w1);
                *(uint32_t*)(smem + SM_A + mhi * 272 + n0 * 2) = *(uint32_t*)&hh;
            }
        } else {
            const float* w3 = smf + 1152;
            float pl = 0.f, ph = 0.f;
#pragma unroll
            for (int nt = 0; nt < 16; nt++) {
                int n0 = nt * 8 + c2;
                float ga0 = pg[n0], ga1 = pg[n0 + 1], ea0 = pe[n0], ea1 = pe[n0 + 1];
                float w30 = w3[n0], w31 = w3[n0 + 1];
                pl += fmaxf((acc[nt][0] - mul) * rsl * ga0 + ea0, 0.f) * w30
                    + fmaxf((acc[nt][1] - mul) * rsl * ga1 + ea1, 0.f) * w31;
                ph += fmaxf((acc[nt][2] - muh) * rsh * ga0 + ea0, 0.f) * w30
                    + fmaxf((acc[nt][3] - muh) * rsh * ga1 + ea1, 0.f) * w31;
            }
#pragma unroll
            for (int o = 1; o <= 2; o <<= 1) {
                pl += __shfl_xor_sync(0xffffffffu, pl, o);
                ph += __shfl_xor_sync(0xffffffffu, ph, o);
            }
            if ((lane & 3) == 0) {
                float bb3 = smf[1280];
                int el = base + mlo; if (el < E) out[el] = pl + bb3;
                int eh = base + mhi; if (eh < E) out[eh] = ph + bb3;
            }
        }
    };

    auto zero_acc = [&]() {
#pragma unroll
        for (int i = 0; i < 16; i++)
#pragma unroll
            for (int j = 0; j < 4; j++) acc[i][j] = 0.f;
    };

    // layer 0 epilogue -> layer 1
    epilogue(0, false);
    zero_acc();
    stage_b(3);
    __syncthreads();
    mma_chunk();
    __syncthreads();

    // layer 1 epilogue -> layer 2
    epilogue(1, false);
    zero_acc();
    stage_b(4);
    __syncthreads();
    mma_chunk();
    __syncthreads();

    // final: LN + matvec W3 + b3
    epilogue(2, true);
}

extern "C" void kernel_launch(void* const* d_in, const int* in_sizes, int n_in,
                              void* d_out, int out_size) {
    const float* x    = (const float*)d_in[0];
    const int*   ei   = (const int*)d_in[1];
    const float* edge = (const float*)d_in[2];
    const float* W0   = (const float*)d_in[3];
    const float* b0   = (const float*)d_in[4];
    const float* g0   = (const float*)d_in[5];
    const float* be0  = (const float*)d_in[6];
    const float* W1   = (const float*)d_in[7];
    const float* b1   = (const float*)d_in[8];
    const float* g1   = (const float*)d_in[9];
    const float* be1  = (const float*)d_in[10];
    const float* W2   = (const float*)d_in[11];
    const float* b2   = (const float*)d_in[12];
    const float* g2   = (const float*)d_in[13];
    const float* be2  = (const float*)d_in[14];
    const float* W3   = (const float*)d_in[15];
    const float* b3   = (const float*)d_in[16];

    int E = out_size;

    prep_kernel<<<(5 * 16384 + 255) / 256, 256>>>(W0, W1, W2);

    cudaFuncSetAttribute(edge_mlp_hmma,
                         cudaFuncAttributeMaxDynamicSharedMemorySize, SM_TOTAL);
    dim3 grid((E + BM - 1) / BM);
    edge_mlp_hmma<<<grid, TPB, SM_TOTAL>>>(
        (float*)d_out, x, ei, edge,
        b0, g0, be0, b1, g1, be1, b2, g2, be2, W3, b3, E);
}

// round 4
// speedup vs baseline: 5.0352x; 1.4875x over previous
#include <cuda_runtime.h>
#include <cuda_fp16.h>
#include <cstdint>

#define TPB    256
#define BM     128
#define H      128
#define LDAH   136          // padded row stride in halves (272B: conflict-free ldmatrix)
#define LN_EPS 1e-5f

// SMEM layout (bytes)
#define SM_PAR   0          // 1281 floats of params
#define SM_RED   5632       // LN partial exchange: 2*128 float2 = 2048B
#define SM_A     8192       // 128 x LDAH halves = 34816B
#define SM_B     43008      // 2 buffers x 34816B
#define SM_BUF   34816
#define SM_TOTAL (43008 + 2 * 34816)   // 112640

// 5 pre-transposed fp16 weight tiles: [tile][n=128][k=128]
__device__ __align__(16) __half g_wt[5 * 16384];

__device__ __forceinline__ uint32_t smem_u32(const void* p) {
    uint32_t a;
    asm("{ .reg .u64 t; cvta.to.shared.u64 t, %1; cvt.u32.u64 %0, t; }"
        : "=r"(a) : "l"(p));
    return a;
}

#define LDMATRIX_X4(r0, r1, r2, r3, addr)                                      \
    asm volatile("ldmatrix.sync.aligned.m8n8.x4.shared.b16 {%0,%1,%2,%3}, [%4];" \
                 : "=r"(r0), "=r"(r1), "=r"(r2), "=r"(r3) : "r"(addr))

#define MMA16816(d, a0, a1, a2, a3, bb0, bb1)                                  \
    asm volatile("mma.sync.aligned.m16n8k16.row.col.f32.f16.f16.f32 "          \
                 "{%0,%1,%2,%3}, {%4,%5,%6,%7}, {%8,%9}, {%0,%1,%2,%3};"       \
                 : "+f"((d)[0]), "+f"((d)[1]), "+f"((d)[2]), "+f"((d)[3])      \
                 : "r"(a0), "r"(a1), "r"(a2), "r"(a3), "r"(bb0), "r"(bb1))

#define CP_ASYNC16(dst, src)                                                   \
    asm volatile("cp.async.cg.shared.global [%0], [%1], 16;" :: "r"(dst), "l"(src))
#define CP_COMMIT()  asm volatile("cp.async.commit_group;" ::: "memory")
#define CP_WAIT0()   asm volatile("cp.async.wait_group 0;" ::: "memory")

// ---------------- prep: transpose + fp16-convert weights ----------------
__global__ void prep_kernel(const float* __restrict__ W0,
                            const float* __restrict__ W1,
                            const float* __restrict__ W2) {
    int idx = blockIdx.x * blockDim.x + threadIdx.x;
    if (idx >= 5 * 16384) return;
    int t = idx >> 14, r = idx & 16383, n = r >> 7, k = r & 127;
    float v;
    if (t < 3)       v = W0[(t * 128 + k) * 128 + n];
    else if (t == 3) v = W1[k * 128 + n];
    else             v = W2[k * 128 + n];
    g_wt[idx] = __float2half_rn(v);
}

// ---------------- main fused kernel ----------------
extern "C" __global__ void __launch_bounds__(TPB, 2)
edge_mlp_hmma2(float* __restrict__ out,
               const float* __restrict__ x, const int* __restrict__ ei,
               const float* __restrict__ edge,
               const float* __restrict__ b0, const float* __restrict__ g0, const float* __restrict__ be0,
               const float* __restrict__ b1, const float* __restrict__ g1, const float* __restrict__ be1,
               const float* __restrict__ b2, const float* __restrict__ g2, const float* __restrict__ be2,
               const float* __restrict__ W3, const float* __restrict__ b3,
               int E) {
    extern __shared__ char smem[];
    float* smf = (float*)smem;
    const uint32_t sb = smem_u32(smem);
    const int tid = threadIdx.x, wid = tid >> 5, lane = tid & 31;
    const int mi = wid & 3, ni = wid >> 2;       // warp grid: 4 m-strips x 2 n-strips
    const int base = blockIdx.x * BM;

    // stage LN params + W3/b3 (fp32)
    for (int i = tid; i < 128; i += TPB) {
        smf[0 * 384 + i] = b0[i]; smf[0 * 384 + 128 + i] = g0[i]; smf[0 * 384 + 256 + i] = be0[i];
        smf[1 * 384 + i] = b1[i]; smf[1 * 384 + 128 + i] = g1[i]; smf[1 * 384 + 256 + i] = be1[i];
        smf[2 * 384 + i] = b2[i]; smf[2 * 384 + 128 + i] = g2[i]; smf[2 * 384 + 256 + i] = be2[i];
        smf[1152 + i] = W3[i];
    }
    if (tid == 0) smf[1280] = b3[0];

    // ldmatrix lane addressing
    const int arow = (lane & 7) + ((lane >> 3) & 1) * 8;
    const int acol = (lane >> 4) * 8;
    const uint32_t aaddr0 = sb + SM_A +
        (uint32_t)((mi * 32 + arow) * LDAH + acol) * 2;
    const uint32_t aaddr1 = aaddr0 + 16 * LDAH * 2;
    const int bn = (lane & 7) + ((lane >> 4) & 1) * 8;
    const int bk = ((lane >> 3) & 1) * 8;
    const uint32_t bbase = sb + SM_B + (uint32_t)((ni * 64 + bn) * LDAH + bk) * 2;

    float acc[2][8][4];
#pragma unroll
    for (int a = 0; a < 2; a++)
#pragma unroll
        for (int t = 0; t < 8; t++)
#pragma unroll
            for (int j = 0; j < 4; j++) acc[a][t][j] = 0.f;

    auto zero_acc = [&]() {
#pragma unroll
        for (int a = 0; a < 2; a++)
#pragma unroll
            for (int t = 0; t < 8; t++)
#pragma unroll
                for (int j = 0; j < 4; j++) acc[a][t][j] = 0.f;
    };

    auto stage_b = [&](int t, int buf) {
        const char* src = (const char*)(g_wt + t * 16384);
        uint32_t dst = sb + SM_B + buf * SM_BUF;
#pragma unroll
        for (int i = 0; i < 8; i++) {
            int u = tid + i * 256;
            CP_ASYNC16(dst + (u >> 4) * 272 + (u & 15) * 16, src + u * 16);
        }
        CP_COMMIT();
    };

    auto gather = [&](int g) {
        for (int r = 0; r < 16; r++) {
            int m = wid * 16 + r;
            int e = base + m; if (e >= E) e = E - 1;
            const float* src;
            if (g == 0)      src = x + (size_t)ei[e] * H;
            else if (g == 1) src = x + (size_t)ei[(size_t)E + e] * H;
            else             src = edge + (size_t)e * H;
            float4 v = __ldg((const float4*)src + lane);
            __half2 h0 = __floats2half2_rn(v.x, v.y);
            __half2 h1 = __floats2half2_rn(v.z, v.w);
            uint2 u = make_uint2(*(uint32_t*)&h0, *(uint32_t*)&h1);
            *(uint2*)(smem + SM_A + m * 272 + lane * 8) = u;
        }
    };

    auto mma_chunk = [&](uint32_t bufo) {
#pragma unroll
        for (int ks = 0; ks < 8; ks++) {
            uint32_t A0[4], A1[4];
            LDMATRIX_X4(A0[0], A0[1], A0[2], A0[3], aaddr0 + ks * 32);
            LDMATRIX_X4(A1[0], A1[1], A1[2], A1[3], aaddr1 + ks * 32);
#pragma unroll
            for (int g = 0; g < 4; g++) {
                uint32_t Bf[4];
                LDMATRIX_X4(Bf[0], Bf[1], Bf[2], Bf[3],
                            bbase + bufo + g * (16 * LDAH * 2) + ks * 32);
                MMA16816(acc[0][2 * g],     A0[0], A0[1], A0[2], A0[3], Bf[0], Bf[1]);
                MMA16816(acc[0][2 * g + 1], A0[0], A0[1], A0[2], A0[3], Bf[2], Bf[3]);
                MMA16816(acc[1][2 * g],     A1[0], A1[1], A1[2], A1[3], Bf[0], Bf[1]);
                MMA16816(acc[1][2 * g + 1], A1[0], A1[1], A1[2], A1[3], Bf[2], Bf[3]);
            }
        }
    };

    const int c2 = 2 * (lane & 3);
    const int r4 = lane >> 2;
    float2* red = (float2*)(smem + SM_RED);

    // thread's row for slot (am, h): mi*32 + am*16 + r4 + h*8
    auto epilogue = [&](int l, bool last) {
        const float* pb = smf + l * 384;
        const float* pg = pb + 128;
        const float* pe = pb + 256;
        float s1[2][2], s2[2][2];
#pragma unroll
        for (int am = 0; am < 2; am++)
#pragma unroll
            for (int h = 0; h < 2; h++) { s1[am][h] = 0.f; s2[am][h] = 0.f; }
#pragma unroll
        for (int nt = 0; nt < 8; nt++) {
            int n0 = ni * 64 + nt * 8 + c2;
            float bia0 = pb[n0], bia1 = pb[n0 + 1];
#pragma unroll
            for (int am = 0; am < 2; am++)
#pragma unroll
                for (int h = 0; h < 2; h++) {
                    float v0 = acc[am][nt][2 * h]     + bia0;
                    float v1 = acc[am][nt][2 * h + 1] + bia1;
                    acc[am][nt][2 * h] = v0; acc[am][nt][2 * h + 1] = v1;
                    s1[am][h] += v0 + v1;
                    s2[am][h] += v0 * v0 + v1 * v1;
                }
        }
#pragma unroll
        for (int o = 1; o <= 2; o <<= 1)
#pragma unroll
            for (int am = 0; am < 2; am++)
#pragma unroll
                for (int h = 0; h < 2; h++) {
                    s1[am][h] += __shfl_xor_sync(0xffffffffu, s1[am][h], o);
                    s2[am][h] += __shfl_xor_sync(0xffffffffu, s2[am][h], o);
                }
        if ((lane & 3) == 0) {
#pragma unroll
            for (int am = 0; am < 2; am++)
#pragma unroll
                for (int h = 0; h < 2; h++) {
                    int row = mi * 32 + am * 16 + r4 + h * 8;
                    red[ni * 128 + row] = make_float2(s1[am][h], s2[am][h]);
                }
        }
        __syncthreads();
        float mu[2][2], rs[2][2];
#pragma unroll
        for (int am = 0; am < 2; am++)
#pragma unroll
            for (int h = 0; h < 2; h++) {
                int row = mi * 32 + am * 16 + r4 + h * 8;
                float2 p0 = red[row], p1 = red[128 + row];
                float t1 = p0.x + p1.x, t2 = p0.y + p1.y;
                float m_ = t1 * (1.0f / 128.0f);
                mu[am][h] = m_;
                rs[am][h] = rsqrtf(t2 * (1.0f / 128.0f) - m_ * m_ + LN_EPS);
            }
        if (!last) {
#pragma unroll
            for (int nt = 0; nt < 8; nt++) {
                int n0 = ni * 64 + nt * 8 + c2;
                float ga0 = pg[n0], ga1 = pg[n0 + 1];
                float ea0 = pe[n0], ea1 = pe[n0 + 1];
#pragma unroll
                for (int am = 0; am < 2; am++)
#pragma unroll
                    for (int h = 0; h < 2; h++) {
                        int row = mi * 32 + am * 16 + r4 + h * 8;
                        float v0 = fmaxf((acc[am][nt][2 * h]     - mu[am][h]) * rs[am][h] * ga0 + ea0, 0.f);
                        float v1 = fmaxf((acc[am][nt][2 * h + 1] - mu[am][h]) * rs[am][h] * ga1 + ea1, 0.f);
                        __half2 hv = __floats2half2_rn(v0, v1);
                        *(uint32_t*)(smem + SM_A + row * 272 + n0 * 2) = *(uint32_t*)&hv;
                    }
            }
            __syncthreads();
        } else {
            const float* w3 = smf + 1152;
            float p[2][2];
#pragma unroll
            for (int am = 0; am < 2; am++)
#pragma unroll
                for (int h = 0; h < 2; h++) p[am][h] = 0.f;
#pragma unroll
            for (int nt = 0; nt < 8; nt++) {
                int n0 = ni * 64 + nt * 8 + c2;
                float ga0 = pg[n0], ga1 = pg[n0 + 1];
                float ea0 = pe[n0], ea1 = pe[n0 + 1];
                float w30 = w3[n0], w31 = w3[n0 + 1];
#pragma unroll
                for (int am = 0; am < 2; am++)
#pragma unroll
                    for (int h = 0; h < 2; h++) {
                        p[am][h] += fmaxf((acc[am][nt][2 * h]     - mu[am][h]) * rs[am][h] * ga0 + ea0, 0.f) * w30
                                  + fmaxf((acc[am][nt][2 * h + 1] - mu[am][h]) * rs[am][h] * ga1 + ea1, 0.f) * w31;
                    }
            }
#pragma unroll
            for (int o = 1; o <= 2; o <<= 1)
#pragma unroll
                for (int am = 0; am < 2; am++)
#pragma unroll
                    for (int h = 0; h < 2; h++)
                        p[am][h] += __shfl_xor_sync(0xffffffffu, p[am][h], o);
            __syncthreads();   // all stats reads done before red reuse
            if ((lane & 3) == 0) {
#pragma unroll
                for (int am = 0; am < 2; am++)
#pragma unroll
                    for (int h = 0; h < 2; h++) {
                        int row = mi * 32 + am * 16 + r4 + h * 8;
                        red[ni * 128 + row].x = p[am][h];
                    }
            }
            __syncthreads();
            if (ni == 0 && (lane & 3) == 0) {
                float bb3 = smf[1280];
#pragma unroll
                for (int am = 0; am < 2; am++)
#pragma unroll
                    for (int h = 0; h < 2; h++) {
                        int row = mi * 32 + am * 16 + r4 + h * 8;
                        int e = base + row;
                        if (e < E) out[e] = red[row].x + red[128 + row].x + bb3;
                    }
            }
        }
    };

    // ---------------- pipeline ----------------
    stage_b(0, 0);
    gather(0);
    CP_WAIT0(); __syncthreads();

    stage_b(1, 1);                 // overlap with MMA chunk 0
    mma_chunk(0);
    __syncthreads();
    gather(1);
    CP_WAIT0(); __syncthreads();

    stage_b(2, 0);
    mma_chunk(SM_BUF);
    __syncthreads();
    gather(2);
    CP_WAIT0(); __syncthreads();

    stage_b(3, 1);
    mma_chunk(0);
    epilogue(0, false);            // internal syncs; writes A
    CP_WAIT0(); __syncthreads();

    stage_b(4, 0);
    zero_acc();
    mma_chunk(SM_BUF);
    epilogue(1, false);
    CP_WAIT0(); __syncthreads();

    zero_acc();
    mma_chunk(0);
    epilogue(2, true);
}

extern "C" void kernel_launch(void* const* d_in, const int* in_sizes, int n_in,
                              void* d_out, int out_size) {
    const float* x    = (const float*)d_in[0];
    const int*   ei   = (const int*)d_in[1];
    const float* edge = (const float*)d_in[2];
    const float* W0   = (const float*)d_in[3];
    const float* b0   = (const float*)d_in[4];
    const float* g0   = (const float*)d_in[5];
    const float* be0  = (const float*)d_in[6];
    const float* W1   = (const float*)d_in[7];
    const float* b1   = (const float*)d_in[8];
    const float* g1   = (const float*)d_in[9];
    const float* be1  = (const float*)d_in[10];
    const float* W2   = (const float*)d_in[11];
    const float* b2   = (const float*)d_in[12];
    const float* g2   = (const float*)d_in[13];
    const float* be2  = (const float*)d_in[14];
    const float* W3   = (const float*)d_in[15];
    const float* b3   = (const float*)d_in[16];

    int E = out_size;

    prep_kernel<<<(5 * 16384 + 255) / 256, 256>>>(W0, W1, W2);

    cudaFuncSetAttribute(edge_mlp_hmma2,
                         cudaFuncAttributeMaxDynamicSharedMemorySize, SM_TOTAL);
    dim3 grid((E + BM - 1) / BM);
    edge_mlp_hmma2<<<grid, TPB, SM_TOTAL>>>(
        (float*)d_out, x, ei, edge,
        b0, g0, be0, b1, g1, be1, b2, g2, be2, W3, b3, E);
}